// round 1
// baseline (speedup 1.0000x reference)
#include <cuda_runtime.h>
#include <math.h>
#include <stdint.h>

// Problem constants
#define BATCH    512
#define SEQT     25
#define CH       512
#define NWIN     5
#define POOLW    5          // SEQT / NWIN
#define BS       2560       // BATCH * NWIN
#define NROWS    5120       // 2 * BS
#define TEMP_INV 10.0f
#define SHIFT    10.0f      // logits bounded by |cos|/T <= 10

// GEMM tiling
#define TM 128
#define TN 128
#define TK 32

// Scratch (device globals; no allocation allowed)
__device__ float g_zn[NROWS * CH];     // normalized pooled rows, fp32 (10 MB -> lives in L2)
__device__ float g_rowS[NROWS];        // per-row sum of exp(logit - SHIFT), excl. diagonal
__device__ float g_rowPos[NROWS];      // per-row positive logit

// ---------------------------------------------------------------------------
// Kernel 0: zero the row accumulators (must run every replay)
// ---------------------------------------------------------------------------
__global__ void init_kernel() {
    int i = blockIdx.x * blockDim.x + threadIdx.x;
    if (i < NROWS) g_rowS[i] = 0.0f;
}

// ---------------------------------------------------------------------------
// Kernel A: adaptive-avg-pool (5-wide bins) + L2 normalize. One block per
// output row (5120 blocks x 128 threads, 4 channels per thread).
// ---------------------------------------------------------------------------
__global__ __launch_bounds__(128) void pool_norm_kernel(const float* __restrict__ zi,
                                                        const float* __restrict__ zj) {
    int r  = blockIdx.x;                       // 0..5119
    const float* src = (r < BS) ? zi : zj;
    int rr = (r < BS) ? r : r - BS;
    int b  = rr / NWIN;
    int w  = rr % NWIN;
    const float* base = src + ((size_t)(b * SEQT + w * POOLW)) * CH;

    int c0 = threadIdx.x * 4;
    float4 acc = make_float4(0.f, 0.f, 0.f, 0.f);
#pragma unroll
    for (int t = 0; t < POOLW; t++) {
        float4 v = *(const float4*)(base + (size_t)t * CH + c0);
        acc.x += v.x; acc.y += v.y; acc.z += v.z; acc.w += v.w;
    }
    acc.x *= 0.2f; acc.y *= 0.2f; acc.z *= 0.2f; acc.w *= 0.2f;

    float ss = acc.x * acc.x + acc.y * acc.y + acc.z * acc.z + acc.w * acc.w;
#pragma unroll
    for (int o = 16; o > 0; o >>= 1) ss += __shfl_xor_sync(0xffffffffu, ss, o);

    __shared__ float wsum[4];
    if ((threadIdx.x & 31) == 0) wsum[threadIdx.x >> 5] = ss;
    __syncthreads();
    float tot = wsum[0] + wsum[1] + wsum[2] + wsum[3];

    float inv = 1.0f / fmaxf(sqrtf(tot), 1e-8f);
    float4 o4 = make_float4(acc.x * inv, acc.y * inv, acc.z * inv, acc.w * inv);
    *(float4*)(g_zn + (size_t)r * CH + c0) = o4;
}

// ---------------------------------------------------------------------------
// Kernel B: fused symmetric Gram tiles + exp + row/col sum scatter.
// Grid (40, 40): block (ct, rt) active iff ct >= rt (upper triangle).
// Each block: 128x128 tile of sim, fp32 SGEMM (8x8 per thread), then epilogue
// computes e = exp(logit - SHIFT), accumulates row sums (and col sums for
// off-diagonal tiles, exploiting sim symmetry), and extracts positives.
// ---------------------------------------------------------------------------
__global__ __launch_bounds__(256) void simclr_tile_kernel() {
    int ct = blockIdx.x, rt = blockIdx.y;
    if (ct < rt) return;
    bool diag = (ct == rt);

    __shared__ float As[TK][TM];
    __shared__ float Bs[TK][TN];
    __shared__ float colsmem[TN];
    __shared__ float rowsmem[TM];

    int tid = threadIdx.x;
    int tx = tid & 15, ty = tid >> 4;

    float acc[8][8];
#pragma unroll
    for (int i = 0; i < 8; i++)
#pragma unroll
        for (int j = 0; j < 8; j++) acc[i][j] = 0.f;

    const float* Ag = g_zn + (size_t)rt * TM * CH;
    const float* Bg = g_zn + (size_t)ct * TN * CH;

    for (int k0 = 0; k0 < CH; k0 += TK) {
        __syncthreads();
#pragma unroll
        for (int it = 0; it < 4; it++) {
            int idx = it * 256 + tid;         // 0..1023 float4 slots
            int row = idx >> 3;               // 0..127
            int k4  = (idx & 7) * 4;          // 0..28
            float4 va = *(const float4*)(Ag + (size_t)row * CH + k0 + k4);
            As[k4 + 0][row] = va.x; As[k4 + 1][row] = va.y;
            As[k4 + 2][row] = va.z; As[k4 + 3][row] = va.w;
            float4 vb = *(const float4*)(Bg + (size_t)row * CH + k0 + k4);
            Bs[k4 + 0][row] = vb.x; Bs[k4 + 1][row] = vb.y;
            Bs[k4 + 2][row] = vb.z; Bs[k4 + 3][row] = vb.w;
        }
        __syncthreads();

#pragma unroll
        for (int kk = 0; kk < TK; kk++) {
            float a[8], b[8];
            *(float4*)(a)     = *(const float4*)&As[kk][ty * 4];
            *(float4*)(a + 4) = *(const float4*)&As[kk][64 + ty * 4];
            *(float4*)(b)     = *(const float4*)&Bs[kk][tx * 4];
            *(float4*)(b + 4) = *(const float4*)&Bs[kk][64 + tx * 4];
#pragma unroll
            for (int i = 0; i < 8; i++)
#pragma unroll
                for (int j = 0; j < 8; j++) acc[i][j] += a[i] * b[j];
        }
    }

    // ---- epilogue ----
    if (tid < TN) colsmem[tid] = 0.f;
    __syncthreads();

    int gr0 = rt * TM, gc0 = ct * TN;
    int Rr[8], Cc[8];
#pragma unroll
    for (int i = 0; i < 8; i++) {
        Rr[i] = (i < 4) ? (ty * 4 + i) : (64 + ty * 4 + i - 4);
        Cc[i] = (i < 4) ? (tx * 4 + i) : (64 + tx * 4 + i - 4);
    }

    float rowpart[8], colpart[8];
#pragma unroll
    for (int i = 0; i < 8; i++) { rowpart[i] = 0.f; colpart[i] = 0.f; }

#pragma unroll
    for (int i = 0; i < 8; i++) {
        int gi = gr0 + Rr[i];
#pragma unroll
        for (int j = 0; j < 8; j++) {
            int gj = gc0 + Cc[j];
            float logit = acc[i][j] * TEMP_INV;
            float e = (gi == gj) ? 0.f : __expf(logit - SHIFT);
            rowpart[i] += e;
            colpart[j] += e;
            if (gj == gi + BS) {        // positives (and, by symmetry, gj's positive = gi)
                g_rowPos[gi] = logit;
                g_rowPos[gj] = logit;
            }
        }
    }

    // reduce rowpart across tx (lanes differing in bits 0..3)
#pragma unroll
    for (int i = 0; i < 8; i++) {
#pragma unroll
        for (int o = 1; o < 16; o <<= 1)
            rowpart[i] += __shfl_xor_sync(0xffffffffu, rowpart[i], o);
    }
    if (tx == 0) {
#pragma unroll
        for (int i = 0; i < 8; i++) rowsmem[Rr[i]] = rowpart[i];   // unique writer per row
    }

    // reduce colpart across the two ty values in this warp (bit 4)
#pragma unroll
    for (int j = 0; j < 8; j++)
        colpart[j] += __shfl_xor_sync(0xffffffffu, colpart[j], 16);
    if ((tid & 16) == 0) {                // one lane set per warp holds combined values
#pragma unroll
        for (int j = 0; j < 8; j++) atomicAdd(&colsmem[Cc[j]], colpart[j]);
    }
    __syncthreads();

    if (tid < TM) {
        atomicAdd(&g_rowS[gr0 + tid], rowsmem[tid]);
        if (!diag) atomicAdd(&g_rowS[gc0 + tid], colsmem[tid]);
    }
}

// ---------------------------------------------------------------------------
// Kernel C: finalize. loss = (1/N) * sum_i [SHIFT + log(S_i) - pos_i]
// ---------------------------------------------------------------------------
__global__ __launch_bounds__(512) void finalize_kernel(float* __restrict__ out) {
    int tid = threadIdx.x;
    float part = 0.f;
    for (int i = tid; i < NROWS; i += 512)
        part += SHIFT + logf(g_rowS[i]) - g_rowPos[i];

#pragma unroll
    for (int o = 16; o > 0; o >>= 1) part += __shfl_xor_sync(0xffffffffu, part, o);

    __shared__ float wsum[16];
    if ((tid & 31) == 0) wsum[tid >> 5] = part;
    __syncthreads();
    if (tid == 0) {
        float tot = 0.f;
#pragma unroll
        for (int w = 0; w < 16; w++) tot += wsum[w];
        out[0] = tot / (float)NROWS;
    }
}

// ---------------------------------------------------------------------------
extern "C" void kernel_launch(void* const* d_in, const int* in_sizes, int n_in,
                              void* d_out, int out_size) {
    const float* zi = (const float*)d_in[0];
    const float* zj = (const float*)d_in[1];
    float* out = (float*)d_out;

    init_kernel<<<(NROWS + 255) / 256, 256>>>();
    pool_norm_kernel<<<NROWS, 128>>>(zi, zj);
    dim3 grid(NROWS / TN, NROWS / TM);
    simclr_tile_kernel<<<grid, 256>>>();
    finalize_kernel<<<1, 512>>>(out);
}

// round 3
// speedup vs baseline: 5.3003x; 5.3003x over previous
#include <cuda_runtime.h>
#include <cuda_bf16.h>
#include <math.h>
#include <stdint.h>

// ---------------- problem constants ----------------
#define BATCH    512
#define SEQT     25
#define CH       512
#define NWIN     5
#define POOLW    5
#define BS       2560          // BATCH * NWIN
#define NROWS    5120          // 2 * BS
#define NT       40            // 128-row tiles per dim
#define TM       128
#define TEMP_INV 10.0f
#define SHIFT    10.0f
#define LDA      72            // padded smem row stride (bf16 elems): 144B, conflict-free LDSM

// ---------------- device scratch ----------------
__device__ __align__(16) __nv_bfloat16 g_znh[NROWS * CH];  // normalized rows, bf16
__device__ float g_rowS[NROWS];     // sum_j exp(logit-SHIFT), j != i
__device__ float g_rowPos[NROWS];   // positive logit per row

static __device__ __forceinline__ uint32_t smem_u32(const void* p) {
    uint32_t r;
    asm("{ .reg .u64 t; cvta.to.shared.u64 t, %1; cvt.u32.u64 %0, t; }" : "=r"(r) : "l"(p));
    return r;
}

#define LDSM_X4(R, addr) \
    asm volatile("ldmatrix.sync.aligned.m8n8.x4.shared.b16 {%0,%1,%2,%3}, [%4];" \
                 : "=r"((R)[0]), "=r"((R)[1]), "=r"((R)[2]), "=r"((R)[3]) : "r"(addr))

#define MMA16816(C, A, B0, B1) \
    asm volatile("mma.sync.aligned.m16n8k16.row.col.f32.bf16.bf16.f32 " \
                 "{%0,%1,%2,%3}, {%4,%5,%6,%7}, {%8,%9}, {%0,%1,%2,%3};" \
                 : "+f"((C)[0]), "+f"((C)[1]), "+f"((C)[2]), "+f"((C)[3]) \
                 : "r"((A)[0]), "r"((A)[1]), "r"((A)[2]), "r"((A)[3]), \
                   "r"(B0), "r"(B1))

// ---------------------------------------------------------------------------
// Kernel 0: zero accumulators + output (every replay)
// ---------------------------------------------------------------------------
__global__ void init_kernel(float* out) {
    int i = blockIdx.x * blockDim.x + threadIdx.x;
    if (i < NROWS) g_rowS[i] = 0.0f;
    if (i == 0) out[0] = 0.0f;
}

// ---------------------------------------------------------------------------
// Kernel A: adaptive-avg-pool + L2 normalize -> bf16 rows
// ---------------------------------------------------------------------------
__global__ __launch_bounds__(128) void pool_norm_kernel(const float* __restrict__ zi,
                                                        const float* __restrict__ zj) {
    int r  = blockIdx.x;
    const float* src = (r < BS) ? zi : zj;
    int rr = (r < BS) ? r : r - BS;
    int b  = rr / NWIN;
    int w  = rr % NWIN;
    const float* base = src + ((size_t)(b * SEQT + w * POOLW)) * CH;

    int c0 = threadIdx.x * 4;
    float4 acc = make_float4(0.f, 0.f, 0.f, 0.f);
#pragma unroll
    for (int t = 0; t < POOLW; t++) {
        float4 v = *(const float4*)(base + (size_t)t * CH + c0);
        acc.x += v.x; acc.y += v.y; acc.z += v.z; acc.w += v.w;
    }
    acc.x *= 0.2f; acc.y *= 0.2f; acc.z *= 0.2f; acc.w *= 0.2f;

    float ss = acc.x * acc.x + acc.y * acc.y + acc.z * acc.z + acc.w * acc.w;
#pragma unroll
    for (int o = 16; o > 0; o >>= 1) ss += __shfl_xor_sync(0xffffffffu, ss, o);

    __shared__ float wsum[4];
    if ((threadIdx.x & 31) == 0) wsum[threadIdx.x >> 5] = ss;
    __syncthreads();
    float tot = wsum[0] + wsum[1] + wsum[2] + wsum[3];

    float inv = 1.0f / fmaxf(sqrtf(tot), 1e-8f);
    __nv_bfloat162 p0 = __floats2bfloat162_rn(acc.x * inv, acc.y * inv);
    __nv_bfloat162 p1 = __floats2bfloat162_rn(acc.z * inv, acc.w * inv);
    __nv_bfloat16* dst = g_znh + (size_t)r * CH + c0;
    *(__nv_bfloat162*)(dst)     = p0;
    *(__nv_bfloat162*)(dst + 2) = p1;
}

// ---------------------------------------------------------------------------
// Kernel B: HMMA bf16 Gram tiles (upper triangle) + fused exp / row+col sums.
// 256 threads, 8 warps; warp (wr=wid&3, wc=wid>>2) computes rows wr*32..+32,
// cols wc*64..+64 of the 128x128 tile. K chunks of 64 staged in smem.
// ---------------------------------------------------------------------------
__global__ __launch_bounds__(256, 2) void simclr_hmma_kernel() {
    int ct = blockIdx.x, rt = blockIdx.y;
    if (ct < rt) return;
    const bool diag = (ct == rt);
    const bool haspos = (ct == rt + 20);      // +BS = 20 tiles

    __shared__ __align__(16) __nv_bfloat16 As[TM * LDA];
    __shared__ __align__(16) __nv_bfloat16 Bsm[TM * LDA];
    __shared__ float rowsm[TM];
    __shared__ float colsm[TM];

    int tid = threadIdx.x;
    int wid = tid >> 5, lid = tid & 31;
    int wr = wid & 3, wc = wid >> 2;
    int g = lid >> 2, t4 = lid & 3;

    if (tid < TM) { rowsm[tid] = 0.f; colsm[tid] = 0.f; }

    float acc[2][8][4];
#pragma unroll
    for (int mi = 0; mi < 2; mi++)
#pragma unroll
        for (int na = 0; na < 8; na++)
#pragma unroll
            for (int q = 0; q < 4; q++) acc[mi][na][q] = 0.f;

    const __nv_bfloat16* Ag = g_znh + (size_t)rt * TM * CH;
    const __nv_bfloat16* Bg = g_znh + (size_t)ct * TM * CH;
    uint32_t aBase = smem_u32(As), bBase = smem_u32(Bsm);

    for (int k0 = 0; k0 < CH; k0 += 64) {
        __syncthreads();
#pragma unroll
        for (int it = 0; it < 4; it++) {
            int idx = tid + it * 256;            // 0..1023
            int row = idx >> 3, ch = idx & 7;
            *(uint4*)((char*)As  + row * 144 + ch * 16) =
                *(const uint4*)(Ag + (size_t)row * CH + k0 + ch * 8);
            *(uint4*)((char*)Bsm + row * 144 + ch * 16) =
                *(const uint4*)(Bg + (size_t)row * CH + k0 + ch * 8);
        }
        __syncthreads();

#pragma unroll
        for (int ks = 0; ks < 4; ks++) {
            int kk = ks * 16;
            uint32_t a[2][4];
#pragma unroll
            for (int mi = 0; mi < 2; mi++) {
                int r = wr * 32 + mi * 16 + (lid & 15);
                LDSM_X4(a[mi], aBase + r * 144 + (kk + (lid >> 4) * 8) * 2);
            }
            uint32_t bfr[4][4];
#pragma unroll
            for (int nb = 0; nb < 4; nb++) {
                int r = wc * 64 + nb * 16 + (lid & 15);
                LDSM_X4(bfr[nb], bBase + r * 144 + (kk + (lid >> 4) * 8) * 2);
            }
#pragma unroll
            for (int mi = 0; mi < 2; mi++)
#pragma unroll
                for (int na = 0; na < 8; na++)
                    MMA16816(acc[mi][na], a[mi], bfr[na >> 1][na & 1], bfr[na >> 1][2 + (na & 1)]);
        }
    }
    __syncthreads();

    // ---- fused epilogue ----
    int gr0 = rt * TM, gc0 = ct * TM;
    float colacc[16];
#pragma unroll
    for (int q = 0; q < 16; q++) colacc[q] = 0.f;
    float rowpart[2][2] = {{0.f, 0.f}, {0.f, 0.f}};

#pragma unroll
    for (int mi = 0; mi < 2; mi++) {
#pragma unroll
        for (int na = 0; na < 8; na++) {
#pragma unroll
            for (int q = 0; q < 4; q++) {
                int h = q >> 1, e = q & 1;
                int rl = wr * 32 + mi * 16 + g + h * 8;
                int cl = wc * 64 + na * 8 + t4 * 2 + e;
                float sim = acc[mi][na][q];
                float ev = __expf(sim * TEMP_INV - SHIFT);
                if (diag && rl == cl) ev = 0.f;
                if (haspos && rl == cl) {
                    float lg = sim * TEMP_INV;
                    g_rowPos[gr0 + rl] = lg;
                    g_rowPos[gr0 + rl + BS] = lg;
                }
                rowpart[mi][h] += ev;
                colacc[na * 2 + e] += ev;
            }
        }
    }

    // row sums: reduce over t4 lanes (xor 1, 2)
#pragma unroll
    for (int mi = 0; mi < 2; mi++)
#pragma unroll
        for (int h = 0; h < 2; h++) {
            float v = rowpart[mi][h];
            v += __shfl_xor_sync(0xffffffffu, v, 1);
            v += __shfl_xor_sync(0xffffffffu, v, 2);
            if (t4 == 0) atomicAdd(&rowsm[wr * 32 + mi * 16 + g + h * 8], v);
        }

    // col sums: reduce over g lanes (xor 4, 8, 16)
#pragma unroll
    for (int q = 0; q < 16; q++) {
        float v = colacc[q];
        v += __shfl_xor_sync(0xffffffffu, v, 4);
        v += __shfl_xor_sync(0xffffffffu, v, 8);
        v += __shfl_xor_sync(0xffffffffu, v, 16);
        if (g == 0) atomicAdd(&colsm[wc * 64 + (q >> 1) * 8 + t4 * 2 + (q & 1)], v);
    }
    __syncthreads();

    if (tid < TM) {
        atomicAdd(&g_rowS[gr0 + tid], rowsm[tid]);
        if (!diag) atomicAdd(&g_rowS[gc0 + tid], colsm[tid]);
    }
}

// ---------------------------------------------------------------------------
// Kernel C: finalize. loss = (1/N) * sum_i [SHIFT + log(S_i) - pos_i]
// ---------------------------------------------------------------------------
__global__ __launch_bounds__(512) void finalize_kernel(float* __restrict__ out) {
    int i = blockIdx.x * 512 + threadIdx.x;
    float part = SHIFT + __logf(g_rowS[i]) - g_rowPos[i];

#pragma unroll
    for (int o = 16; o > 0; o >>= 1) part += __shfl_xor_sync(0xffffffffu, part, o);

    __shared__ float wsum[16];
    if ((threadIdx.x & 31) == 0) wsum[threadIdx.x >> 5] = part;
    __syncthreads();
    if (threadIdx.x == 0) {
        float tot = 0.f;
#pragma unroll
        for (int w = 0; w < 16; w++) tot += wsum[w];
        atomicAdd(out, tot / (float)NROWS);
    }
}

// ---------------------------------------------------------------------------
extern "C" void kernel_launch(void* const* d_in, const int* in_sizes, int n_in,
                              void* d_out, int out_size) {
    const float* zi = (const float*)d_in[0];
    const float* zj = (const float*)d_in[1];
    float* out = (float*)d_out;

    init_kernel<<<(NROWS + 255) / 256, 256>>>(out);
    pool_norm_kernel<<<NROWS, 128>>>(zi, zj);
    dim3 grid(NT, NT);
    simclr_hmma_kernel<<<grid, 256>>>();
    finalize_kernel<<<NROWS / 512, 512>>>(out);
}